// round 2
// baseline (speedup 1.0000x reference)
#include <cuda_runtime.h>
#include <math.h>

// iDDPMPrecond: (c_skip=1, c_out=-s, c_in=1/sqrt(s^2+1), c_noise=M-1-argmin_j|s-u_j|)
//
// Closed form: the reference recurrence telescopes to 1+u[j]^2 = A/alpha_bar(j),
// A = alpha_bar(M), alpha_bar(j) = sin^2(c*j), c = pi/(2*M*(1+C2)).
// (The C1 clamp only affects u[0].) Invert analytically to get a candidate index,
// then verify a +/-2 window against the ACTUAL u table for exact argmin semantics
// (first-index tie-break). No smem, no barrier, no dependent search chain.

__global__ void precond_kernel(const float* __restrict__ sigma,
                               const float* __restrict__ u,
                               float* __restrict__ out,
                               int B, int M, int skip_count,
                               float A, float inv_c)
{
    int tid = blockIdx.x * blockDim.x + threadIdx.x;

    // c_skip region (scalar or broadcast): 1.0f
    if (tid < skip_count) out[tid] = 1.0f;
    if (tid >= B) return;

    float s = sigma[tid];
    out[skip_count + tid]     = -s;                     // c_out
    out[skip_count + B + tid] = rsqrtf(fmaf(s, s, 1.0f));  // c_in

    // Analytic candidate index: j_real = asin(sqrt(A/(1+s^2))) / c
    float x  = sqrtf(A / fmaf(s, s, 1.0f));   // in (0,1)
    float jf = asinf(x) * inv_c;
    int jc = (int)(jf + 0.5f);
    if (jc < 0) jc = 0;
    if (jc > M) jc = M;

    // Exact argmin over window [jc-2, jc+2] clamped; 5 independent L1/L2 loads.
    int k0 = jc - 2; if (k0 < 0) k0 = 0;
    int k4 = jc + 2; if (k4 > M) k4 = M;

    int   best_j = k0;
    float best_d = fabsf(s - __ldg(&u[k0]));
    #pragma unroll
    for (int t = 1; t < 5; t++) {
        int k = k0 + t;
        if (k <= k4) {
            float d = fabsf(s - __ldg(&u[k]));
            if (d < best_d) { best_d = d; best_j = k; }  // strict < keeps first index on ties
        }
    }

    out[skip_count + 2 * B + tid] = (float)(M - 1 - best_j);  // c_noise
}

extern "C" void kernel_launch(void* const* d_in, const int* in_sizes, int n_in,
                              void* d_out, int out_size)
{
    // inputs per metadata order: x (unused), sigma, u, M
    const float* sigma = (const float*)d_in[1];
    const float* u     = (const float*)d_in[2];
    const int B  = in_sizes[1];
    const int nU = in_sizes[2];
    const int M  = nU - 1;

    // Flattened tuple layout: [c_skip (skip elems)] [c_out B] [c_in B] [c_noise B]
    int skip = out_size - 3 * B;
    if (skip < 0) skip = 0;

    const double C2    = 0.008;
    const double c     = 3.14159265358979323846 * 0.5 / ((double)M * (1.0 + C2));
    const double sM    = sin(c * (double)M);
    const float  A     = (float)(sM * sM);       // alpha_bar(M)
    const float  inv_c = (float)(1.0 / c);

    const int threads = 256;
    const int blocks  = (B + threads - 1) / threads;
    precond_kernel<<<blocks, threads>>>(sigma, u, (float*)d_out, B, M, skip, A, inv_c);
}

// round 3
// speedup vs baseline: 1.0435x; 1.0435x over previous
#include <cuda_runtime.h>
#include <math.h>

// iDDPMPrecond: (c_skip=1, c_out=-s, c_in=1/sqrt(s^2+1), c_noise=M-1-argmin_j|s-u_j|)
//
// Closed form: recurrence telescopes to 1+u[j]^2 = A/alpha_bar(j), A=alpha_bar(M),
// alpha_bar(j)=sin^2(c*j), c=pi/(2*M*(1+C2)). Invert analytically:
//   j_real = asin(sqrt(A) * rsqrt(1+s^2)) / c       (note: reuses c_in!)
// Max index error ~0.005, so verify only a +/-1 window (3 probes) against the
// ACTUAL u table for exact argmin semantics (strict < keeps first index on ties).

__global__ __launch_bounds__(256)
void precond_kernel(const float* __restrict__ sigma,
                    const float* __restrict__ u,
                    float* __restrict__ out,
                    int B, int M, int skip_count,
                    float sqrtA, float inv_c)
{
    int tid = blockIdx.x * blockDim.x + threadIdx.x;

    // c_skip region (scalar or broadcast): 1.0f
    if (tid < skip_count) out[tid] = 1.0f;
    if (tid >= B) return;

    float s  = sigma[tid];
    float ci = rsqrtf(fmaf(s, s, 1.0f));     // c_in
    out[skip_count + tid]     = -s;          // c_out
    out[skip_count + B + tid] = ci;          // c_in

    // Analytic candidate index (reuse ci): x = sqrt(A/(1+s^2)) = sqrtA * ci
    float jf = asinf(sqrtA * ci) * inv_c;
    int jc = __float2int_rn(jf);
    if (jc < 1)     jc = 1;        // window becomes [0..2]
    if (jc > M - 1) jc = M - 1;    // window becomes [M-2..M]

    // Exact argmin over [jc-1, jc+1]; 3 independent cached loads.
    float d0 = fabsf(s - __ldg(&u[jc - 1]));
    float d1 = fabsf(s - __ldg(&u[jc]));
    float d2 = fabsf(s - __ldg(&u[jc + 1]));

    int   best_j = jc - 1;
    float best_d = d0;
    if (d1 < best_d) { best_d = d1; best_j = jc; }
    if (d2 < best_d) {              best_j = jc + 1; }

    out[skip_count + 2 * B + tid] = (float)(M - 1 - best_j);  // c_noise
}

extern "C" void kernel_launch(void* const* d_in, const int* in_sizes, int n_in,
                              void* d_out, int out_size)
{
    // inputs per metadata order: x (unused), sigma, u, M
    const float* sigma = (const float*)d_in[1];
    const float* u     = (const float*)d_in[2];
    const int B  = in_sizes[1];
    const int nU = in_sizes[2];
    const int M  = nU - 1;

    // Flattened tuple layout: [c_skip (skip elems)] [c_out B] [c_in B] [c_noise B]
    int skip = out_size - 3 * B;
    if (skip < 0) skip = 0;

    const double C2    = 0.008;
    const double c     = 3.14159265358979323846 * 0.5 / ((double)M * (1.0 + C2));
    const double sM    = sin(c * (double)M);
    const float  sqrtA = (float)sM;          // sqrt(alpha_bar(M)) = sin(c*M)
    const float  inv_c = (float)(1.0 / c);

    const int threads = 256;
    const int blocks  = (B + threads - 1) / threads;
    precond_kernel<<<blocks, threads>>>(sigma, u, (float*)d_out, B, M, skip, sqrtA, inv_c);
}